// round 4
// baseline (speedup 1.0000x reference)
#include <cuda_runtime.h>
#include <cuda_bf16.h>

// YOLOv1 loss — persistent blocks, WARP-autonomous cp.async double-buffered
// pipelines (no block barriers in the hot loop), single launch.
// N = 802816 cells x 30 fp32 channels (P and T). 25088 warp-tiles of 32 cells.

#define NCELL  (16384 * 7 * 7)        // 802816
#define BLK    128
#define WARPS  (BLK / 32)             // 4
#define GRID   444                    // 3 blocks/SM * 148 SMs
#define WTILE  32                     // cells per warp-tile
#define NWT    (NCELL / WTILE)        // 25088
#define WSTRIDE (GRID * WARPS)        // 1776
#define WFL    (WTILE * 30)           // floats per tile per tensor (960)
#define WF4    (WFL / 4)              // float4 per tile per tensor (240)
#define WBUF   (2 * WFL)              // floats per stage (P+T) = 1920
#define SMEM_BYTES (WARPS * 2 * WBUF * 4)   // 4 warps * 2 stages * 7680 B = 61440

__device__ float4 g_part[GRID];
__device__ unsigned int g_count = 0;

__device__ __forceinline__ void cp16(float4* dst_smem, const float4* src_gmem) {
    unsigned int d = (unsigned int)__cvta_generic_to_shared(dst_smem);
    asm volatile("cp.async.cg.shared.global [%0], [%1], 16;\n" :: "r"(d), "l"(src_gmem));
}
__device__ __forceinline__ void cp_commit() { asm volatile("cp.async.commit_group;\n"); }
__device__ __forceinline__ void cp_wait1()  { asm volatile("cp.async.wait_group 1;\n"); }
__device__ __forceinline__ void cp_wait0()  { asm volatile("cp.async.wait_group 0;\n"); }

__device__ __forceinline__ void prefetch_wtile(float* buf, int wt,
                                               const float* P, const float* T, int lane)
{
    const float4* gp = (const float4*)(P + (size_t)wt * WFL);
    const float4* gt = (const float4*)(T + (size_t)wt * WFL);
    float4* d = (float4*)buf;
    #pragma unroll
    for (int i = 0; i < (2 * WF4) / 32; ++i) {        // 15 iterations
        int idx = lane + i * 32;                       // 0..479
        const float4* src = (idx < WF4) ? (gp + idx) : (gt + (idx - WF4));
        cp16(d + idx, src);
    }
}

__global__ __launch_bounds__(BLK) void yolo_fused(const float* __restrict__ P,
                                                  const float* __restrict__ T,
                                                  float* __restrict__ out)
{
    extern __shared__ float smem[];   // [warp][stage][P(960) | T(960)]
    const int tid  = threadIdx.x;
    const int wid  = tid >> 5;
    const int lane = tid & 31;
    const float CELL = 1.0f / 7.0f;

    float* wbase = smem + wid * (2 * WBUF);

    float ax = 0.0f, ay = 0.0f, az = 0.0f, aw = 0.0f;

    const int gw = blockIdx.x * WARPS + wid;          // global warp id, < WSTRIDE
    int wt = gw;
    int s = 0;
    prefetch_wtile(wbase, wt, P, T, lane);            // gw < NWT always
    cp_commit();

    for (; wt < NWT; wt += WSTRIDE) {
        const int nx = wt + WSTRIDE;
        if (nx < NWT) prefetch_wtile(wbase + (s ^ 1) * WBUF, nx, P, T, lane);
        cp_commit();                                  // commit (possibly empty) group
        cp_wait1();                                   // current tile's copy done
        __syncwarp();

        const float* p = wbase + s * WBUF + lane * 30;
        const float* t = p + WFL;

        const float t0 = t[0], t1 = t[1], t2 = t[2], t3 = t[3], tc = t[4];

        // target corners — faithful to the reference's in-place bug:
        //   xy1 = xy*CELL - wh*0.5 ;  xy2 = xy1*CELL + wh*0.5
        const float twx = t2 * t2, twy = t3 * t3;
        const float tx1 = t0 * CELL - 0.5f * twx;
        const float ty1 = t1 * CELL - 0.5f * twy;
        const float tx2 = tx1 * CELL + 0.5f * twx;
        const float ty2 = ty1 * CELL + 0.5f * twy;
        const float area_t = (tx2 - tx1) * (ty2 - ty1);

        float iou0, iou1;
        #pragma unroll
        for (int b = 0; b < 2; ++b) {
            const float px = p[b * 5 + 0], py = p[b * 5 + 1];
            const float pw = p[b * 5 + 2], ph = p[b * 5 + 3];
            const float pwx = pw * pw, pwy = ph * ph;
            const float x1 = px * CELL - 0.5f * pwx;
            const float y1 = py * CELL - 0.5f * pwy;
            const float x2 = x1 * CELL + 0.5f * pwx;
            const float y2 = y1 * CELL + 0.5f * pwy;
            const float ltx = fmaxf(x1, tx1), lty = fmaxf(y1, ty1);
            const float rbx = fminf(x2, tx2), rby = fminf(y2, ty2);
            const float dx = fmaxf(rbx - ltx, 0.0f);
            const float dy = fmaxf(rby - lty, 0.0f);
            const float inter  = dx * dy;
            const float area_p = (x2 - x1) * (y2 - y1);
            const float v = inter / (area_p + area_t - inter);
            if (b == 0) iou0 = v; else iou1 = v;
        }
        const int b5 = (iou1 > iou0) ? 5 : 0;         // first max wins ties

        // class column: first max over t[10:30]
        int kcol = 10;
        float vb = t[10];
        #pragma unroll
        for (int k = 11; k < 30; ++k) {
            float v = t[k];
            if (v > vb) { vb = v; kcol = k; }
        }

        const bool obj = (tc == 1.0f);
        const bool noo = (tc == 0.0f);

        const float dk = p[kcol]   - t[kcol];
        const float dc = p[b5 + 4] - t[b5 + 4];
        const float d0 = p[b5 + 0] - t[b5 + 0];
        const float d1 = p[b5 + 1] - t[b5 + 1];
        const float d2 = p[b5 + 2] - t[b5 + 2];
        const float d3 = p[b5 + 3] - t[b5 + 3];
        const float d4 = p[4] - tc;
        const float d9 = p[9] - t[9];

        if (obj) {
            ax += dk * dk;                                   // cls
            ay += dc * dc;                                   // conf
            az += d0 * d0 + d1 * d1 + d2 * d2 + d3 * d3;     // center+wh
        }
        if (noo) aw += d4 * d4 + d9 * d9;                    // noobj

        __syncwarp();                                 // all lanes done reading stage s
        s ^= 1;
    }
    cp_wait0();                                       // drain pending async copies

    // ---- block reduce (once per block) ----
    #pragma unroll
    for (int o = 16; o > 0; o >>= 1) {
        ax += __shfl_down_sync(0xffffffffu, ax, o);
        ay += __shfl_down_sync(0xffffffffu, ay, o);
        az += __shfl_down_sync(0xffffffffu, az, o);
        aw += __shfl_down_sync(0xffffffffu, aw, o);
    }
    __shared__ float4 wsum[WARPS];
    __shared__ bool s_last;
    if (lane == 0) wsum[wid] = make_float4(ax, ay, az, aw);
    __syncthreads();
    if (tid == 0) {
        float4 sv = wsum[0];
        #pragma unroll
        for (int w = 1; w < WARPS; ++w) {
            sv.x += wsum[w].x; sv.y += wsum[w].y;
            sv.z += wsum[w].z; sv.w += wsum[w].w;
        }
        __stcg(&g_part[blockIdx.x], sv);
        __threadfence();
        unsigned int prev = atomicAdd(&g_count, 1u);
        s_last = (prev == (unsigned int)(GRID - 1));
    }
    __syncthreads();
    if (!s_last) return;

    // ---- last block: fp64 reduction of 444 partials ----
    double a0 = 0.0, a1 = 0.0, a2 = 0.0, a3 = 0.0;
    for (int i = tid; i < GRID; i += BLK) {
        const float4 v = __ldcg(&g_part[i]);
        a0 += (double)v.x; a1 += (double)v.y;
        a2 += (double)v.z; a3 += (double)v.w;
    }
    __shared__ double s0[BLK], s1[BLK], s2[BLK], s3[BLK];
    s0[tid] = a0; s1[tid] = a1; s2[tid] = a2; s3[tid] = a3;
    __syncthreads();
    #pragma unroll
    for (int o = BLK / 2; o > 0; o >>= 1) {
        if (tid < o) {
            s0[tid] += s0[tid + o]; s1[tid] += s1[tid + o];
            s2[tid] += s2[tid + o]; s3[tid] += s3[tid + o];
        }
        __syncthreads();
    }
    if (tid == 0) {
        const float cls = (float)(5.0 * s0[0]);   // lambda_coord
        const float cnf = (float)(5.0 * s1[0]);
        const float cwh = (float)(5.0 * s2[0]);
        const float nob = (float)(0.5 * s3[0]);   // lambda_noobj
        out[0] = cls;
        out[1] = cnf;
        out[2] = cwh;
        out[3] = nob + cls + cnf + cwh;           // total
        g_count = 0;                              // reset for next graph replay
    }
}

extern "C" void kernel_launch(void* const* d_in, const int* in_sizes, int n_in,
                              void* d_out, int out_size)
{
    const float* P = (const float*)d_in[0];   // predictions [B,S,S,30] fp32
    const float* T = (const float*)d_in[1];   // targets     [B,S,S,30] fp32
    float* out = (float*)d_out;               // [cls, conf, center+wh, total]

    cudaFuncSetAttribute(yolo_fused, cudaFuncAttributeMaxDynamicSharedMemorySize,
                         SMEM_BYTES);
    yolo_fused<<<GRID, BLK, SMEM_BYTES>>>(P, T, out);
}

// round 5
// speedup vs baseline: 1.1136x; 1.1136x over previous
#include <cuda_runtime.h>
#include <cuda_bf16.h>

// YOLOv1 loss — persistent blocks, register-landing-zone prefetch:
// each thread holds the NEXT tile's 15 float4 in registers (LDG in flight
// through the compute phase), STS to a single smem stage, compute, repeat.
// 5 blocks/SM * 4 warps = 20 warps/SM; ~154 KB of LDG in flight per SM.

#define NCELL  (16384 * 7 * 7)       // 802816
#define BLK    128
#define BPSM   5
#define GRID   (148 * BPSM)          // 740 persistent blocks
#define TILE   128                   // cells per block-tile
#define NTILE  (NCELL / TILE)        // 6272
#define TFL    (TILE * 30)           // floats per tensor per tile (3840)
#define TF4    (TFL / 4)             // float4 per tensor per tile (960)
#define NLD    15                    // float4 per thread per tile (2*TF4/BLK)

__device__ float4 g_part[GRID];
__device__ unsigned int g_count = 0;

__global__ __launch_bounds__(BLK, BPSM)
void yolo_fused(const float* __restrict__ P,
                const float* __restrict__ T,
                float* __restrict__ out)
{
    __shared__ float buf[2 * TFL];    // [ P(3840) | T(3840) ]  30720 B
    const int tid = threadIdx.x;
    const float CELL = 1.0f / 7.0f;

    float ax = 0.0f, ay = 0.0f, az = 0.0f, aw = 0.0f;

    float4 r[NLD];                    // landing zone for next tile

    int tile = blockIdx.x;
    // prologue: load first tile into regs (front-batched LDG.128, MLP=15)
    {
        const float4* gp = (const float4*)(P + (size_t)tile * TFL);
        const float4* gt = (const float4*)(T + (size_t)tile * TFL);
        #pragma unroll
        for (int i = 0; i < NLD; ++i) {
            const int idx = tid + i * BLK;            // 0..1919
            r[i] = (idx < TF4) ? __ldg(gp + idx) : __ldg(gt + (idx - TF4));
        }
    }

    for (; tile < NTILE; tile += GRID) {
        // deposit current tile's regs into smem
        float4* b4 = (float4*)buf;
        #pragma unroll
        for (int i = 0; i < NLD; ++i) b4[tid + i * BLK] = r[i];

        // issue next tile's loads NOW — in flight during compute below
        const int nx = tile + GRID;
        if (nx < NTILE) {
            const float4* gp = (const float4*)(P + (size_t)nx * TFL);
            const float4* gt = (const float4*)(T + (size_t)nx * TFL);
            #pragma unroll
            for (int i = 0; i < NLD; ++i) {
                const int idx = tid + i * BLK;
                r[i] = (idx < TF4) ? __ldg(gp + idx) : __ldg(gt + (idx - TF4));
            }
        }
        __syncthreads();              // smem stage fully written

        const float* p = buf + tid * 30;
        const float* t = p + TFL;

        const float t0 = t[0], t1 = t[1], t2 = t[2], t3 = t[3], tc = t[4];

        // target corners — faithful to the reference's in-place bug:
        //   xy1 = xy*CELL - wh*0.5 ;  xy2 = xy1*CELL + wh*0.5
        const float twx = t2 * t2, twy = t3 * t3;
        const float tx1 = t0 * CELL - 0.5f * twx;
        const float ty1 = t1 * CELL - 0.5f * twy;
        const float tx2 = tx1 * CELL + 0.5f * twx;
        const float ty2 = ty1 * CELL + 0.5f * twy;
        const float area_t = (tx2 - tx1) * (ty2 - ty1);

        float iou0, iou1;
        #pragma unroll
        for (int b = 0; b < 2; ++b) {
            const float px = p[b * 5 + 0], py = p[b * 5 + 1];
            const float pw = p[b * 5 + 2], ph = p[b * 5 + 3];
            const float pwx = pw * pw, pwy = ph * ph;
            const float x1 = px * CELL - 0.5f * pwx;
            const float y1 = py * CELL - 0.5f * pwy;
            const float x2 = x1 * CELL + 0.5f * pwx;
            const float y2 = y1 * CELL + 0.5f * pwy;
            const float ltx = fmaxf(x1, tx1), lty = fmaxf(y1, ty1);
            const float rbx = fminf(x2, tx2), rby = fminf(y2, ty2);
            const float dx = fmaxf(rbx - ltx, 0.0f);
            const float dy = fmaxf(rby - lty, 0.0f);
            const float inter  = dx * dy;
            const float area_p = (x2 - x1) * (y2 - y1);
            const float v = inter / (area_p + area_t - inter);
            if (b == 0) iou0 = v; else iou1 = v;
        }
        const int b5 = (iou1 > iou0) ? 5 : 0;         // first max wins ties

        // class column: first max over t[10:30]
        int kcol = 10;
        float vb = t[10];
        #pragma unroll
        for (int k = 11; k < 30; ++k) {
            float v = t[k];
            if (v > vb) { vb = v; kcol = k; }
        }

        const bool obj = (tc == 1.0f);
        const bool noo = (tc == 0.0f);

        const float dk = p[kcol]   - t[kcol];
        const float dc = p[b5 + 4] - t[b5 + 4];
        const float d0 = p[b5 + 0] - t[b5 + 0];
        const float d1 = p[b5 + 1] - t[b5 + 1];
        const float d2 = p[b5 + 2] - t[b5 + 2];
        const float d3 = p[b5 + 3] - t[b5 + 3];
        const float d4 = p[4] - tc;
        const float d9 = p[9] - t[9];

        if (obj) {
            ax += dk * dk;                                   // cls
            ay += dc * dc;                                   // conf
            az += d0 * d0 + d1 * d1 + d2 * d2 + d3 * d3;     // center+wh
        }
        if (noo) aw += d4 * d4 + d9 * d9;                    // noobj

        __syncthreads();              // all warps done reading buf
    }

    // ---- block reduce (once per block) ----
    #pragma unroll
    for (int o = 16; o > 0; o >>= 1) {
        ax += __shfl_down_sync(0xffffffffu, ax, o);
        ay += __shfl_down_sync(0xffffffffu, ay, o);
        az += __shfl_down_sync(0xffffffffu, az, o);
        aw += __shfl_down_sync(0xffffffffu, aw, o);
    }
    __shared__ float4 wsum[BLK / 32];
    __shared__ bool s_last;
    if ((tid & 31) == 0) wsum[tid >> 5] = make_float4(ax, ay, az, aw);
    __syncthreads();
    if (tid == 0) {
        float4 sv = wsum[0];
        #pragma unroll
        for (int w = 1; w < BLK / 32; ++w) {
            sv.x += wsum[w].x; sv.y += wsum[w].y;
            sv.z += wsum[w].z; sv.w += wsum[w].w;
        }
        __stcg(&g_part[blockIdx.x], sv);
        __threadfence();
        unsigned int prev = atomicAdd(&g_count, 1u);
        s_last = (prev == (unsigned int)(GRID - 1));
    }
    __syncthreads();
    if (!s_last) return;

    // ---- last block: fp64 reduction of 740 partials (reuse buf as smem) ----
    double a0 = 0.0, a1 = 0.0, a2 = 0.0, a3 = 0.0;
    for (int i = tid; i < GRID; i += BLK) {
        const float4 v = __ldcg(&g_part[i]);
        a0 += (double)v.x; a1 += (double)v.y;
        a2 += (double)v.z; a3 += (double)v.w;
    }
    double* s0 = (double*)buf;        // 4 * 128 doubles = 4096 B, fits in buf
    double* s1 = s0 + BLK;
    double* s2 = s1 + BLK;
    double* s3 = s2 + BLK;
    s0[tid] = a0; s1[tid] = a1; s2[tid] = a2; s3[tid] = a3;
    __syncthreads();
    #pragma unroll
    for (int o = BLK / 2; o > 0; o >>= 1) {
        if (tid < o) {
            s0[tid] += s0[tid + o]; s1[tid] += s1[tid + o];
            s2[tid] += s2[tid + o]; s3[tid] += s3[tid + o];
        }
        __syncthreads();
    }
    if (tid == 0) {
        const float cls = (float)(5.0 * s0[0]);   // lambda_coord
        const float cnf = (float)(5.0 * s1[0]);
        const float cwh = (float)(5.0 * s2[0]);
        const float nob = (float)(0.5 * s3[0]);   // lambda_noobj
        out[0] = cls;
        out[1] = cnf;
        out[2] = cwh;
        out[3] = nob + cls + cnf + cwh;           // total
        g_count = 0;                              // reset for next graph replay
    }
}

extern "C" void kernel_launch(void* const* d_in, const int* in_sizes, int n_in,
                              void* d_out, int out_size)
{
    const float* P = (const float*)d_in[0];   // predictions [B,S,S,30] fp32
    const float* T = (const float*)d_in[1];   // targets     [B,S,S,30] fp32
    float* out = (float*)d_out;               // [cls, conf, center+wh, total]

    yolo_fused<<<GRID, BLK>>>(P, T, out);
}